// round 17
// baseline (speedup 1.0000x reference)
#include <cuda_runtime.h>
#include <cuda_bf16.h>
#include <math.h>
#include <stdint.h>

#define B_ 256

// ---------------- device scratch ----------------
__device__ float g_beff[25];
__device__ uint32_t g_xp[B_ * 22000];                // packed x bf16 h|l<<16
__device__ uint32_t g_y1p[B_ * 330 * 26];            // TRANSPOSED: [b][pos][ch(25)+pad]
__device__ uint32_t g_y2p[B_ * 50 * 107];
__device__ uint32_t g_y3p[B_ * 100 * 32];
__device__ float g_feat[B_ * 1400];
__device__ __align__(16) uint16_t g_w1h[10 * 32 * 40];
__device__ __align__(16) uint16_t g_w1l[10 * 32 * 40];
__device__ __align__(16) uint16_t g_w2th[10 * 32 * 56];
__device__ __align__(16) uint16_t g_w2tl[10 * 32 * 56];
__device__ __align__(16) uint16_t g_w3h[8 * 128 * 72];
__device__ __align__(16) uint16_t g_w3l[8 * 128 * 72];
__device__ __align__(16) uint16_t g_w4h[16 * 256 * 72];
__device__ __align__(16) uint16_t g_w4l[16 * 256 * 72];

__device__ __forceinline__ float elu1(float x) { return x > 0.f ? x : expm1f(x); }

__device__ __forceinline__ uint32_t smem_u32(const void* p) {
    uint32_t a;
    asm("{ .reg .u64 t; cvta.to.shared.u64 t, %1; cvt.u32.u64 %0, t; }" : "=r"(a) : "l"(p));
    return a;
}
__device__ __forceinline__ void cpa16(uint32_t dst, const void* src) {
    asm volatile("cp.async.cg.shared.global [%0], [%1], 16;" :: "r"(dst), "l"(src));
}
#define CP_COMMIT() asm volatile("cp.async.commit_group;" ::: "memory")
#define CP_WAIT0()  asm volatile("cp.async.wait_group 0;" ::: "memory")
__device__ __forceinline__ void ldsm4(uint32_t* r, uint32_t addr) {
    asm volatile("ldmatrix.sync.aligned.m8n8.x4.shared.b16 {%0,%1,%2,%3}, [%4];"
                 : "=r"(r[0]), "=r"(r[1]), "=r"(r[2]), "=r"(r[3]) : "r"(addr));
}
__device__ __forceinline__ void ldsm4t(uint32_t* r, uint32_t addr) {
    asm volatile("ldmatrix.sync.aligned.m8n8.x4.trans.shared.b16 {%0,%1,%2,%3}, [%4];"
                 : "=r"(r[0]), "=r"(r[1]), "=r"(r[2]), "=r"(r[3]) : "r"(addr));
}
__device__ __forceinline__ void mma16816(float* d, const uint32_t* a, const uint32_t* b) {
    asm volatile("mma.sync.aligned.m16n8k16.row.col.f32.bf16.bf16.f32 "
                 "{%0,%1,%2,%3}, {%4,%5,%6,%7}, {%8,%9}, {%0,%1,%2,%3};"
                 : "+f"(d[0]), "+f"(d[1]), "+f"(d[2]), "+f"(d[3])
                 : "r"(a[0]), "r"(a[1]), "r"(a[2]), "r"(a[3]), "r"(b[0]), "r"(b[1]));
}
__device__ __forceinline__ uint32_t pack_bf16_split(float v) {
    __nv_bfloat16 h = __float2bfloat16(v);
    float hf = __bfloat162float(h);
    __nv_bfloat16 l = __float2bfloat16(v - hf);
    uint16_t hb = reinterpret_cast<uint16_t&>(h);
    uint16_t lb = reinterpret_cast<uint16_t&>(l);
    return (uint32_t)hb | ((uint32_t)lb << 16);
}

// ---------------- kernel 0 (merged): x-pack + ALL weight images + beff ----------------
#define PW_X   (B_ * 22000)
#define PW_W3  (PW_X + 73728)
#define PW_W4  (PW_W3 + 294912)
#define PW_W1  (PW_W4 + 12800)
#define PW_W2  (PW_W1 + 17920)
#define PW_BE  (PW_W2 + 25)
__global__ void precompute_all_k(const float* __restrict__ x,
                                 const float* __restrict__ w_time, const float* __restrict__ b_time,
                                 const float* __restrict__ w_spat, const float* __restrict__ b_spat,
                                 const float* __restrict__ w2, const float* __restrict__ w3,
                                 const float* __restrict__ w4)
{
    int idx = blockIdx.x * 256 + threadIdx.x;
    if (idx < PW_X) {
        g_xp[idx] = pack_bf16_split(__ldg(&x[idx]));
    } else if (idx < PW_W3) {
        int i3 = idx - PW_X;
        int ch = i3 / 9216, r = i3 % 9216, row = r / 72, kloc = r % 72;
        int gk = ch * 64 + kloc;
        float v = (kloc < 64 && row < 100 && gk < 500) ? w3[row * 500 + gk] : 0.f;
        uint32_t p = pack_bf16_split(v);
        g_w3h[i3] = (uint16_t)(p & 0xffff);
        g_w3l[i3] = (uint16_t)(p >> 16);
    } else if (idx < PW_W4) {
        int i4 = idx - PW_W3;
        int ch = i4 / 18432, r = i4 % 18432, row = r / 72, kloc = r % 72;
        int gk = ch * 64 + kloc;
        float v = (kloc < 64 && row < 200 && gk < 1000) ? w4[row * 1000 + gk] : 0.f;
        uint32_t p = pack_bf16_split(v);
        g_w4h[i4] = (uint16_t)(p & 0xffff);
        g_w4l[i4] = (uint16_t)(p >> 16);
    } else if (idx < PW_W1) {
        int i1 = idx - PW_W4;
        int kk = i1 / 1280, r = i1 % 1280, c = r / 40, o = r % 40;
        float v = 0.f;
        if (c < 22 && o < 25) {
            #pragma unroll
            for (int oo = 0; oo < 25; oo++)
                v = fmaf(w_spat[o * 550 + oo * 22 + c], w_time[oo * 10 + kk], v);
        }
        uint32_t p = pack_bf16_split(v);
        g_w1h[i1] = (uint16_t)(p & 0xffff);
        g_w1l[i1] = (uint16_t)(p >> 16);
    } else if (idx < PW_W2) {
        int i2 = idx - PW_W1;
        int kk = i2 / 1792, r = i2 % 1792, c = r / 56, o = r % 56;
        float v = (c < 25 && o < 50) ? w2[o * 250 + c * 10 + kk] : 0.f;
        uint32_t p = pack_bf16_split(v);
        g_w2th[i2] = (uint16_t)(p & 0xffff);
        g_w2tl[i2] = (uint16_t)(p >> 16);
    } else if (idx < PW_BE) {
        int p = idx - PW_W2;
        float s = b_spat[p];
        for (int oo = 0; oo < 25; oo++) {
            float w = 0.f;
            for (int c = 0; c < 22; c++) w += w_spat[p * 550 + oo * 22 + c];
            s = fmaf(b_time[oo], w, s);
        }
        g_beff[p] = s;
    }
}

// ---------------- stage 1 (TENSOR, tap-decomposed): g_xp -> y1pT ----------------
#define S1_AH 0
#define S1_AL 16640
#define S1_WH 33280
#define S1_WL 58880
#define S1_SMEM 84480

__global__ __launch_bounds__(384, 2) void stage1_k()
{
    extern __shared__ char smc[];
    const uint32_t sb = smem_u32(smc);
    const int tid = threadIdx.x, wid = tid >> 5, lane = tid & 31;
    const int b = blockIdx.x, tile = blockIdx.y;
    const int m0 = tile * 192;
    __shared__ float bs[25];
    if (tid < 25) bs[tid] = g_beff[tid];

    {
        const float4* srcH = reinterpret_cast<const float4*>(g_w1h);
        const float4* srcL = reinterpret_cast<const float4*>(g_w1l);
        for (int i = tid; i < 1600; i += 384) {
            cpa16(sb + S1_WH + i * 16, srcH + i);
            cpa16(sb + S1_WL + i * 16, srcL + i);
        }
        CP_COMMIT();
    }
    {
        const uint32_t* xb = g_xp + b * 22000;
        #pragma unroll 2
        for (int i = tid; i < 4160; i += 384) {
            int cp = i / 208, r = i - cp * 208;
            int t = m0 + r;
            uint32_t h2 = 0u, l2 = 0u;
            if (cp < 11 && t < 1000) {
                uint32_t p0 = __ldg(&xb[(2 * cp) * 1000 + t]);
                uint32_t p1 = __ldg(&xb[(2 * cp + 1) * 1000 + t]);
                h2 = __byte_perm(p0, p1, 0x5410);
                l2 = __byte_perm(p0, p1, 0x7632);
            }
            reinterpret_cast<uint32_t*>(smc + S1_AH)[r * 20 + cp] = h2;
            reinterpret_cast<uint32_t*>(smc + S1_AL)[r * 20 + cp] = l2;
        }
    }
    CP_WAIT0();
    __syncthreads();

    float d[4][4];
    #pragma unroll
    for (int i = 0; i < 4; i++)
        #pragma unroll
        for (int j = 0; j < 4; j++) d[i][j] = 0.f;

    const uint32_t aOff = ((wid * 16 + ((lane >> 3) & 1) * 8 + (lane & 7)) * 40 + (lane >> 4) * 8) * 2;
    const uint32_t aHb = sb + S1_AH + aOff, aLb = sb + S1_AL + aOff;
    const uint32_t bOff = ((((lane >> 3) & 1) * 8 + (lane & 7)) * 40 + (lane >> 4) * 8) * 2;
    const uint32_t bHb = sb + S1_WH + bOff, bLb = sb + S1_WL + bOff;

    #pragma unroll 1
    for (int kk = 0; kk < 10; kk++) {
        #pragma unroll
        for (int s = 0; s < 2; s++) {
            uint32_t ah[4], al[4];
            ldsm4(ah, aHb + kk * 80 + s * 32);
            ldsm4(al, aLb + kk * 80 + s * 32);
            const uint32_t wb = (uint32_t)kk * 2560 + (uint32_t)s * 1280;
            #pragma unroll
            for (int q = 0; q < 2; q++) {
                uint32_t bh[4], bl[4];
                ldsm4t(bh, bHb + wb + q * 32);
                ldsm4t(bl, bLb + wb + q * 32);
                mma16816(d[2 * q],     ah, bh);
                mma16816(d[2 * q],     al, bh);
                mma16816(d[2 * q],     ah, bl);
                mma16816(d[2 * q + 1], ah, bh + 2);
                mma16816(d[2 * q + 1], al, bh + 2);
                mma16816(d[2 * q + 1], ah, bl + 2);
            }
        }
    }

    __syncthreads();
    float* Dsm = reinterpret_cast<float*>(smc);
    {
        const int mloc = wid * 16 + (lane >> 2);
        const int cb = (lane & 3) * 2;
        #pragma unroll
        for (int q = 0; q < 4; q++) {
            int n = q * 8 + cb;
            Dsm[n * 200 + mloc]           = d[q][0];
            Dsm[(n + 1) * 200 + mloc]     = d[q][1];
            Dsm[n * 200 + mloc + 8]       = d[q][2];
            Dsm[(n + 1) * 200 + mloc + 8] = d[q][3];
        }
    }
    __syncthreads();
    #pragma unroll 1
    for (int i = tid; i < 1664; i += 384) {
        int j = i / 26, o = i - j * 26;
        int tp = tile * 64 + j;
        if (tp < 330) {
            uint32_t pv = 0u;
            if (o < 25) {
                const float* row = Dsm + o * 200 + 3 * j;
                float v = fmaxf(row[0], fmaxf(row[1], row[2])) + bs[o];
                pv = pack_bf16_split(elu1(v));
            }
            g_y1p[b * 8580 + tp * 26 + o] = pv;
        }
    }
}

// ---------------- stage 2 (TENSOR, tap-decomposed, balanced m-split): y1pT -> y2p ----------------
#define S2_AH 0
#define S2_AL 15360
#define S2_WH 30720
#define S2_WL 66560
#define S2_SMEM 102400

__global__ __launch_bounds__(256, 2) void stage2_k(const float* __restrict__ b2)
{
    extern __shared__ char smc[];
    const uint32_t sb = smem_u32(smc);
    const int tid = threadIdx.x, wid = tid >> 5, lane = tid & 31;
    const int b = blockIdx.x, h = blockIdx.y;
    const int base = h ? 174 : 0;
    __shared__ float bs[50];
    if (tid < 50) bs[tid] = __ldg(&b2[tid]);

    {
        const float4* srcH = reinterpret_cast<const float4*>(g_w2th);
        const float4* srcL = reinterpret_cast<const float4*>(g_w2tl);
        for (int i = tid; i < 2240; i += 256) {
            cpa16(sb + S2_WH + i * 16, srcH + i);
            cpa16(sb + S2_WL + i * 16, srcL + i);
        }
        CP_COMMIT();
    }
    {
        const uint32_t* yb = g_y1p + b * 8580;
        #pragma unroll 2
        for (int i = tid; i < 3072; i += 256) {
            int r = i >> 4, cp = i & 15;
            int gp = base + r;
            uint32_t h2 = 0u, l2 = 0u;
            if (gp < 330 && cp < 13) {
                uint32_t p0 = __ldg(&yb[gp * 26 + 2 * cp]);
                uint32_t p1 = __ldg(&yb[gp * 26 + 2 * cp + 1]);
                h2 = __byte_perm(p0, p1, 0x5410);
                l2 = __byte_perm(p0, p1, 0x7632);
            }
            *reinterpret_cast<uint32_t*>(smc + S2_AH + r * 80 + cp * 4) = h2;
            *reinterpret_cast<uint32_t*>(smc + S2_AL + r * 80 + cp * 4) = l2;
        }
    }
    CP_WAIT0();
    __syncthreads();

    float d[2][7][4];
    #pragma unroll
    for (int m = 0; m < 2; m++)
        #pragma unroll
        for (int q = 0; q < 7; q++)
            #pragma unroll
            for (int j = 0; j < 4; j++) d[m][q][j] = 0.f;

    const uint32_t aLane = ((((lane >> 3) & 1) * 8 + (lane & 7)) * 40 + (lane >> 4) * 8) * 2;
    const uint32_t bLane = ((((lane >> 3) & 1) * 8 + (lane & 7)) * 56 + (lane >> 4) * 8) * 2;
    const int ndouble = h ? 2 : 3;
    const bool has2 = (wid < ndouble);

    #pragma unroll 1
    for (int kk = 0; kk < 10; kk++) {
        #pragma unroll
        for (int g = 0; g < 2; g++) {
            uint32_t ah0[4], al0[4], ah1[4], al1[4];
            {
                const uint32_t arow0 = (uint32_t)(wid * 16 + kk) * 80 + (uint32_t)g * 32;
                ldsm4(ah0, sb + S2_AH + arow0 + aLane);
                ldsm4(al0, sb + S2_AL + arow0 + aLane);
            }
            if (has2) {
                const uint32_t arow1 = (uint32_t)((wid + 8) * 16 + kk) * 80 + (uint32_t)g * 32;
                ldsm4(ah1, sb + S2_AH + arow1 + aLane);
                ldsm4(al1, sb + S2_AL + arow1 + aLane);
            }
            uint32_t bh[4][4], bl[4][4];
            const uint32_t wb = sb + (uint32_t)kk * 3584 + (uint32_t)g * (16 * 112) + bLane;
            #pragma unroll
            for (int q = 0; q < 4; q++) {
                ldsm4t(bh[q], S2_WH + wb + q * 32);
                ldsm4t(bl[q], S2_WL + wb + q * 32);
            }
            #pragma unroll
            for (int q = 0; q < 3; q++) {
                mma16816(d[0][2 * q],     ah0, bh[q]);
                mma16816(d[0][2 * q],     al0, bh[q]);
                mma16816(d[0][2 * q],     ah0, bl[q]);
                mma16816(d[0][2 * q + 1], ah0, bh[q] + 2);
                mma16816(d[0][2 * q + 1], al0, bh[q] + 2);
                mma16816(d[0][2 * q + 1], ah0, bl[q] + 2);
            }
            mma16816(d[0][6], ah0, bh[3]);
            mma16816(d[0][6], al0, bh[3]);
            mma16816(d[0][6], ah0, bl[3]);
            if (has2) {
                #pragma unroll
                for (int q = 0; q < 3; q++) {
                    mma16816(d[1][2 * q],     ah1, bh[q]);
                    mma16816(d[1][2 * q],     al1, bh[q]);
                    mma16816(d[1][2 * q],     ah1, bl[q]);
                    mma16816(d[1][2 * q + 1], ah1, bh[q] + 2);
                    mma16816(d[1][2 * q + 1], al1, bh[q] + 2);
                    mma16816(d[1][2 * q + 1], ah1, bl[q] + 2);
                }
                mma16816(d[1][6], ah1, bh[3]);
                mma16816(d[1][6], al1, bh[3]);
                mma16816(d[1][6], ah1, bl[3]);
            }
        }
    }

    __syncthreads();
    float* Dsm = reinterpret_cast<float*>(smc);
    {
        const int r0 = (lane >> 2);
        const int cb = (lane & 3) * 2;
        #pragma unroll
        for (int mt = 0; mt < 2; mt++) {
            if (mt == 1 && !has2) break;
            const int rr = (wid + mt * 8) * 16 + r0;
            #pragma unroll
            for (int q = 0; q < 7; q++) {
                int n = q * 8 + cb;
                Dsm[rr * 56 + n]           = d[mt][q][0];
                Dsm[rr * 56 + n + 1]       = d[mt][q][1];
                Dsm[(rr + 8) * 56 + n]     = d[mt][q][2];
                Dsm[(rr + 8) * 56 + n + 1] = d[mt][q][3];
            }
        }
    }
    __syncthreads();
    const int np = h ? 49 : 58;
    const int pb = h ? 58 : 0;
    const int cnt = 50 * np;
    #pragma unroll 1
    for (int i = tid; i < cnt; i += 256) {
        int o = i / np, j = i - o * np;
        int p = pb + j;
        int ml = 3 * p - base;
        const float* c0 = Dsm + ml * 56 + o;
        float v = fmaxf(c0[0], fmaxf(c0[56], c0[112])) + bs[o];
        g_y2p[b * 5350 + o * 107 + p] = pack_bf16_split(elu1(v));
    }
}

// ---------------- stage 3 (TENSOR, n-split, 64-k chunks): y2p -> y3p ----------------
// grid (256 samples, 2 n-halves of 48 positions). D[128 m][48 n].
// A full 128-row chunk (cp.async), B [64 k][56 u16 stride]; 3 CTAs/SM.
#define S3_AH 0
#define S3_AL 18432
#define S3_BH 36864
#define S3_BL 44032
#define S3_SMEM 51200

__global__ __launch_bounds__(256, 3) void stage3_k(const float* __restrict__ b3)
{
    extern __shared__ char smc[];
    const uint32_t sb = smem_u32(smc);
    const int tid = threadIdx.x, wid = tid >> 5, lane = tid & 31;
    const int b = blockIdx.x, nh = blockIdx.y;
    __shared__ float bs[100];
    if (tid < 100) bs[tid] = __ldg(&b3[tid]);

    // zero-pad B cols 48..55 once
    {
        uint16_t* bhB = reinterpret_cast<uint16_t*>(smc + S3_BH);
        uint16_t* blB = reinterpret_cast<uint16_t*>(smc + S3_BL);
        for (int i = tid; i < 512; i += 256) {
            int r = i >> 3, c = 48 + (i & 7);
            bhB[r * 56 + c] = 0;
            blB[r * 56 + c] = 0;
        }
    }

    float d[6][4];
    #pragma unroll
    for (int i = 0; i < 6; i++)
        #pragma unroll
        for (int j = 0; j < 4; j++) d[i][j] = 0.f;

    const uint32_t aOff = ((wid * 16 + ((lane >> 3) & 1) * 8 + (lane & 7)) * 72 + (lane >> 4) * 8) * 2;
    const uint32_t bOff = ((((lane >> 3) & 1) * 8 + (lane & 7)) * 56 + (lane >> 4) * 8) * 2;
    const uint32_t aH = sb + S3_AH + aOff, aL = sb + S3_AL + aOff;
    const uint32_t bHb = sb + S3_BH + bOff, bLb = sb + S3_BL + bOff;

    const int kloc = tid >> 2, seg = tid & 3;   // k row, 12-col quarter of 48
    uint16_t* bhRow = reinterpret_cast<uint16_t*>(smc + S3_BH) + kloc * 56 + seg * 12;
    uint16_t* blRow = reinterpret_cast<uint16_t*>(smc + S3_BL) + kloc * 56 + seg * 12;

    #pragma unroll 1
    for (int ch = 0; ch < 8; ch++) {
        __syncthreads();
        // A copy async (full 128 rows of this chunk)
        {
            const float4* srcH = reinterpret_cast<const float4*>(g_w3h + ch * 9216);
            const float4* srcL = reinterpret_cast<const float4*>(g_w3l + ch * 9216);
            for (int i = tid; i < 1152; i += 256) {
                cpa16(sb + S3_AH + i * 16, srcH + i);
                cpa16(sb + S3_AL + i * 16, srcL + i);
            }
            CP_COMMIT();
        }
        // B gather: 12 cols per thread, positions nh*48 + seg*12 + j (always in range)
        {
            const int gk = ch * 64 + kloc;
            if (gk < 500) {
                const int c = gk / 10, kk = gk - c * 10;
                const uint32_t* src = g_y2p + b * 5350 + c * 107 + kk + nh * 48 + seg * 12;
                #pragma unroll
                for (int j = 0; j < 12; j += 2) {
                    uint32_t q0 = __ldg(&src[j]);
                    uint32_t q1 = __ldg(&src[j + 1]);
                    *reinterpret_cast<uint32_t*>(bhRow + j) = __byte_perm(q0, q1, 0x5410);
                    *reinterpret_cast<uint32_t*>(blRow + j) = __byte_perm(q0, q1, 0x7632);
                }
            } else {
                #pragma unroll
                for (int j = 0; j < 12; j += 2) {
                    *reinterpret_cast<uint32_t*>(bhRow + j) = 0u;
                    *reinterpret_cast<uint32_t*>(blRow + j) = 0u;
                }
            }
        }
        CP_WAIT0();
        __syncthreads();

        #pragma unroll
        for (int t = 0; t < 4; t++) {
            uint32_t ah[4], al[4];
            ldsm4(ah, aH + t * 32);
            ldsm4(al, aL + t * 32);
            const uint32_t bt = (uint32_t)t * 1792;   // 16 rows * 112 B
            #pragma unroll
            for (int q = 0; q < 3; q++) {
                uint32_t bh[4], bl[4];
                ldsm4t(bh, bHb + bt + q * 32);
                ldsm4t(bl, bLb + bt + q * 32);
                mma16816(d[2 * q],     ah, bh);
                mma16816(d[2 * q],     al, bh);
                mma16816(d[2 * q],     ah, bl);
                mma16816(d[2 * q + 1], ah, bh + 2);
                mma16816(d[2 * q + 1], al, bh + 2);
                mma16816(d[2 * q + 1], ah, bl + 2);
            }
        }
    }

    // epilogue: Dsm [128 o][56] f32, pool 16 outputs per channel
    __syncthreads();
    float* Dsm = reinterpret_cast<float*>(smc);
    {
        const int r0 = wid * 16 + (lane >> 2);
        const int cb = (lane & 3) * 2;
        #pragma unroll
        for (int q = 0; q < 6; q++) {
            int n = q * 8 + cb;
            Dsm[r0 * 56 + n]           = d[q][0];
            Dsm[r0 * 56 + n + 1]       = d[q][1];
            Dsm[(r0 + 8) * 56 + n]     = d[q][2];
            Dsm[(r0 + 8) * 56 + n + 1] = d[q][3];
        }
    }
    __syncthreads();
    #pragma unroll 1
    for (int i = tid; i < 1600; i += 256) {
        int o = i >> 4, t = i & 15;
        const float* c0 = Dsm + o * 56 + 3 * t;
        float v = fmaxf(c0[0], fmaxf(c0[1], c0[2])) + bs[o];
        g_y3p[b * 3200 + o * 32 + nh * 16 + t] = pack_bf16_split(elu1(v));
    }
}

// ---------------- stage 4 (TENSOR, m-split, 64-k chunks): y3p -> feat ----------------
#define S4_AH 0
#define S4_AL 18432
#define S4_BH 36864
#define S4_BL 44032
#define S4_SMEM 51200

__global__ __launch_bounds__(256, 3) void stage4_k(const float* __restrict__ b4)
{
    extern __shared__ char smc[];
    const uint32_t sb = smem_u32(smc);
    const int tid = threadIdx.x, wid = tid >> 5, lane = tid & 31;
    const int s0 = blockIdx.x * 2, h = blockIdx.y;
    const int nrow = h ? 72 : 128;
    __shared__ float bs[128];
    if (tid < 128) bs[tid] = (h * 128 + tid < 200) ? __ldg(&b4[h * 128 + tid]) : 0.f;

    {
        uint16_t* bhB = reinterpret_cast<uint16_t*>(smc + S4_BH);
        uint16_t* blB = reinterpret_cast<uint16_t*>(smc + S4_BL);
        for (int i = tid; i < 512; i += 256) {
            int r = i >> 3, c = 48 + (i & 7);
            bhB[r * 56 + c] = 0;
            blB[r * 56 + c] = 0;
        }
    }

    float d[6][4];
    #pragma unroll
    for (int i = 0; i < 6; i++)
        #pragma unroll
        for (int j = 0; j < 4; j++) d[i][j] = 0.f;

    const uint32_t aOff = ((wid * 16 + ((lane >> 3) & 1) * 8 + (lane & 7)) * 72 + (lane >> 4) * 8) * 2;
    const uint32_t bOff = ((((lane >> 3) & 1) * 8 + (lane & 7)) * 56 + (lane >> 4) * 8) * 2;
    const uint32_t aH = sb + S4_AH + aOff, aL = sb + S4_AL + aOff;
    const uint32_t bHb = sb + S4_BH + bOff, bLb = sb + S4_BL + bOff;

    const int kloc = tid >> 2, q4 = tid & 3;
    const int segq = q4 >> 1, jb = (q4 & 1) * 12;
    uint16_t* bhRow = reinterpret_cast<uint16_t*>(smc + S4_BH) + kloc * 56 + segq * 24 + jb;
    uint16_t* blRow = reinterpret_cast<uint16_t*>(smc + S4_BL) + kloc * 56 + segq * 24 + jb;

    #pragma unroll 1
    for (int ch = 0; ch < 16; ch++) {
        __syncthreads();
        {
            const float4* srcH = reinterpret_cast<const float4*>(g_w4h + ch * 18432 + h * 9216);
            const float4* srcL = reinterpret_cast<const float4*>(g_w4l + ch * 18432 + h * 9216);
            for (int i = tid; i < 1152; i += 256) {
                cpa16(sb + S4_AH + i * 16, srcH + i);
                cpa16(sb + S4_AL + i * 16, srcL + i);
            }
            CP_COMMIT();
        }
        {
            const int gk = ch * 64 + kloc;
            if (gk < 1000) {
                const int c = gk / 10, kk = gk - c * 10;
                const uint32_t* src = g_y3p + (s0 + segq) * 3200 + c * 32 + kk + jb;
                #pragma unroll
                for (int j = 0; j < 12; j += 2) {
                    int gp = jb + j;
                    uint32_t q0 = (gp < 21)     ? __ldg(&src[j])     : 0u;
                    uint32_t q1 = (gp + 1 < 21) ? __ldg(&src[j + 1]) : 0u;
                    *reinterpret_cast<uint32_t*>(bhRow + j) = __byte_perm(q0, q1, 0x5410);
                    *reinterpret_cast<uint32_t*>(blRow + j) = __byte_perm(q0, q1, 0x7632);
                }
            } else {
                #pragma unroll
                for (int j = 0; j < 12; j += 2) {
                    *reinterpret_cast<uint32_t*>(bhRow + j) = 0u;
                    *reinterpret_cast<uint32_t*>(blRow + j) = 0u;
                }
            }
        }
        CP_WAIT0();
        __syncthreads();

        #pragma unroll
        for (int t = 0; t < 4; t++) {
            uint32_t ah[4], al[4];
            ldsm4(ah, aH + t * 32);
            ldsm4(al, aL + t * 32);
            const uint32_t bt = (uint32_t)t * 1792;
            #pragma unroll
            for (int q = 0; q < 3; q++) {
                uint32_t bh[4], bl[4];
                ldsm4t(bh, bHb + bt + q * 32);
                ldsm4t(bl, bLb + bt + q * 32);
                mma16816(d[2 * q],     ah, bh);
                mma16816(d[2 * q],     al, bh);
                mma16816(d[2 * q],     ah, bl);
                mma16816(d[2 * q + 1], ah, bh + 2);
                mma16816(d[2 * q + 1], al, bh + 2);
                mma16816(d[2 * q + 1], ah, bl + 2);
            }
        }
    }

    __syncthreads();
    float* Dsm = reinterpret_cast<float*>(smc);
    {
        const int r0 = wid * 16 + (lane >> 2);
        const int cb = (lane & 3) * 2;
        #pragma unroll
        for (int q = 0; q < 6; q++) {
            int n = q * 8 + cb;
            Dsm[r0 * 56 + n]           = d[q][0];
            Dsm[r0 * 56 + n + 1]       = d[q][1];
            Dsm[(r0 + 8) * 56 + n]     = d[q][2];
            Dsm[(r0 + 8) * 56 + n + 1] = d[q][3];
        }
    }
    __syncthreads();
    const int cnt = nrow * 14;
    #pragma unroll 1
    for (int i = tid; i < cnt; i += 256) {
        int ol = i / 14, r = i - ol * 14, s = r / 7, t = r - s * 7;
        int n = s * 24 + 3 * t;
        float v = fmaxf(Dsm[ol * 56 + n], fmaxf(Dsm[ol * 56 + n + 1], Dsm[ol * 56 + n + 2]))
                  + bs[ol];
        g_feat[(s0 + s) * 1400 + (h * 128 + ol) * 7 + t] = elu1(v);
    }
}

// ---------------- head (float4) ----------------
__global__ void head_k(const int* __restrict__ sid, const float* __restrict__ hW,
                       const float* __restrict__ hB, float* __restrict__ out)
{
    const int b = blockIdx.x;
    const int s = sid[b];
    const float4* f = reinterpret_cast<const float4*>(g_feat + b * 1400);
    const float4* W = reinterpret_cast<const float4*>(hW + s * 5600);
    float acc[4] = {0.f, 0.f, 0.f, 0.f};
    for (int i = threadIdx.x; i < 350; i += blockDim.x) {
        float4 fv = f[i];
        #pragma unroll
        for (int o = 0; o < 4; o++) {
            float4 wv = __ldg(&W[o * 350 + i]);
            acc[o] = fmaf(fv.x, wv.x, fmaf(fv.y, wv.y, fmaf(fv.z, wv.z, fmaf(fv.w, wv.w, acc[o]))));
        }
    }
    #pragma unroll
    for (int off = 16; off > 0; off >>= 1) {
        #pragma unroll
        for (int o = 0; o < 4; o++) acc[o] += __shfl_down_sync(0xFFFFFFFFu, acc[o], off);
    }
    __shared__ float red[4][4];
    const int w = threadIdx.x >> 5, l = threadIdx.x & 31;
    if (l == 0) {
        #pragma unroll
        for (int o = 0; o < 4; o++) red[o][w] = acc[o];
    }
    __syncthreads();
    if (threadIdx.x < 4) {
        int o = threadIdx.x;
        out[b * 4 + o] = red[o][0] + red[o][1] + red[o][2] + red[o][3] + __ldg(&hB[s * 4 + o]);
    }
}

// ---------------- launch ----------------
extern "C" void kernel_launch(void* const* d_in, const int* in_sizes, int n_in,
                              void* d_out, int out_size)
{
    const float* x      = (const float*)d_in[0];
    const int*   sid    = (const int*)  d_in[1];
    const float* w_time = (const float*)d_in[2];
    const float* b_time = (const float*)d_in[3];
    const float* w_spat = (const float*)d_in[4];
    const float* b_spat = (const float*)d_in[5];
    const float* w2     = (const float*)d_in[6];
    const float* b2     = (const float*)d_in[7];
    const float* w3     = (const float*)d_in[8];
    const float* b3     = (const float*)d_in[9];
    const float* w4     = (const float*)d_in[10];
    const float* b4     = (const float*)d_in[11];
    const float* hW     = (const float*)d_in[12];
    const float* hB     = (const float*)d_in[13];
    float* out = (float*)d_out;

    cudaFuncSetAttribute(stage1_k, cudaFuncAttributeMaxDynamicSharedMemorySize, S1_SMEM);
    cudaFuncSetAttribute(stage2_k, cudaFuncAttributeMaxDynamicSharedMemorySize, S2_SMEM);
    cudaFuncSetAttribute(stage3_k, cudaFuncAttributeMaxDynamicSharedMemorySize, S3_SMEM);
    cudaFuncSetAttribute(stage4_k, cudaFuncAttributeMaxDynamicSharedMemorySize, S4_SMEM);

    precompute_all_k<<<(PW_BE + 255) / 256, 256>>>(x, w_time, b_time, w_spat, b_spat, w2, w3, w4);
    stage1_k<<<dim3(B_, 6), 384, S1_SMEM>>>();
    stage2_k<<<dim3(B_, 2), 256, S2_SMEM>>>(b2);
    stage3_k<<<dim3(B_, 2), 256, S3_SMEM>>>(b3);
    stage4_k<<<dim3(128, 2), 256, S4_SMEM>>>(b4);
    head_k<<<B_, 128>>>(sid, hW, hB, out);
}